// round 1
// baseline (speedup 1.0000x reference)
#include <cuda_runtime.h>
#include <cuda_bf16.h>
#include <float.h>

#define T_SEQ   4096
#define DIM     768
#define HEADS   12
#define HEAD_D  64
#define N_QKV   (3 * DIM)          // 2304
#define RMS_EPS 1.1920928955078125e-07f
#define ATTN_SCALE 0.12f

// Scratch: qkv in [3][H][T][64] head-major layout, y in [T][DIM]
__device__ float g_qkv[3 * HEADS * T_SEQ * HEAD_D];
__device__ float g_y[T_SEQ * DIM];

// ---------------------------------------------------------------------------
// GEMM C = A @ B^T  (A: MxK row-major, B: NxK row-major), 64x64 tile, BK=16,
// 256 threads, 4x4 per thread. Two variants: scatter into g_qkv, or plain.
// ---------------------------------------------------------------------------

__device__ __forceinline__ void gemm_tile_compute(
    const float* __restrict__ A, const float* __restrict__ B,
    int K, int m0, int n0, float acc[4][4])
{
    __shared__ float As[64][17];
    __shared__ float Bs[64][17];
    const int tid = threadIdx.x;
    const int tx = tid & 15;
    const int ty = tid >> 4;

    for (int k0 = 0; k0 < K; k0 += 16) {
        // load 64x16 A-tile and B-tile, float4 per thread
        int idx = tid * 4;
        int r = idx >> 4;        // 0..63
        int c = idx & 15;        // 0,4,8,12
        float4 a4 = *(const float4*)&A[(size_t)(m0 + r) * K + k0 + c];
        As[r][c + 0] = a4.x; As[r][c + 1] = a4.y;
        As[r][c + 2] = a4.z; As[r][c + 3] = a4.w;
        float4 b4 = *(const float4*)&B[(size_t)(n0 + r) * K + k0 + c];
        Bs[r][c + 0] = b4.x; Bs[r][c + 1] = b4.y;
        Bs[r][c + 2] = b4.z; Bs[r][c + 3] = b4.w;
        __syncthreads();

        #pragma unroll
        for (int kk = 0; kk < 16; kk++) {
            float a[4], b[4];
            #pragma unroll
            for (int i = 0; i < 4; i++) a[i] = As[4 * ty + i][kk];
            #pragma unroll
            for (int j = 0; j < 4; j++) b[j] = Bs[4 * tx + j][kk];
            #pragma unroll
            for (int i = 0; i < 4; i++)
                #pragma unroll
                for (int j = 0; j < 4; j++)
                    acc[i][j] += a[i] * b[j];
        }
        __syncthreads();
    }
}

// QKV GEMM: A = x [T, DIM], B = qkv_w [2304, DIM]; scatter into [comp*H+h][t][d]
__global__ void gemm_qkv_kernel(const float* __restrict__ A,
                                const float* __restrict__ B)
{
    const int m0 = blockIdx.x * 64;
    const int n0 = blockIdx.y * 64;
    float acc[4][4] = {};
    gemm_tile_compute(A, B, DIM, m0, n0, acc);

    const int tx = threadIdx.x & 15;
    const int ty = threadIdx.x >> 4;
    #pragma unroll
    for (int i = 0; i < 4; i++) {
        int t = m0 + 4 * ty + i;
        #pragma unroll
        for (int j = 0; j < 4; j++) {
            int n = n0 + 4 * tx + j;           // 0..2303
            // layout: block = n/64 (comp*12+h), then [t][d]
            g_qkv[(size_t)(n >> 6) * (T_SEQ * HEAD_D) + (size_t)t * HEAD_D + (n & 63)] = acc[i][j];
        }
    }
}

// Output projection: A = g_y [T, DIM], B = c_proj_w [DIM, DIM]; plain out
__global__ void gemm_proj_kernel(const float* __restrict__ B,
                                 float* __restrict__ C)
{
    const int m0 = blockIdx.x * 64;
    const int n0 = blockIdx.y * 64;
    float acc[4][4] = {};
    gemm_tile_compute(g_y, B, DIM, m0, n0, acc);

    const int tx = threadIdx.x & 15;
    const int ty = threadIdx.x >> 4;
    #pragma unroll
    for (int i = 0; i < 4; i++) {
        int t = m0 + 4 * ty + i;
        #pragma unroll
        for (int j = 0; j < 4; j++) {
            int n = n0 + 4 * tx + j;
            C[(size_t)t * DIM + n] = acc[i][j];
        }
    }
}

// ---------------------------------------------------------------------------
// RMSNorm (per head, D=64) + partial rotary. grid = T, block = 768 (24 warps):
// warp w: comp = w/12 (0=q,1=k), head = w%12. Lane i owns dims i and i+32.
// ---------------------------------------------------------------------------
__global__ void rms_rope_kernel()
{
    const int t    = blockIdx.x;
    const int w    = threadIdx.x >> 5;
    const int lane = threadIdx.x & 31;
    const int comp = w / HEADS;      // 0 = q, 1 = k
    const int h    = w % HEADS;

    float* p = g_qkv + (size_t)(comp * HEADS + h) * (T_SEQ * HEAD_D)
                     + (size_t)t * HEAD_D;
    float v0 = p[lane];
    float v1 = p[lane + 32];

    float ss = v0 * v0 + v1 * v1;
    #pragma unroll
    for (int off = 16; off >= 1; off >>= 1)
        ss += __shfl_xor_sync(0xffffffffu, ss, off);
    float r = rsqrtf(ss * (1.0f / HEAD_D) + RMS_EPS);
    v0 *= r; v1 *= r;

    if (lane < 16) {
        // freqs[i] = (1/1024)^(i/15) = 2^(-10*i/15); i>=16 => freq 0 (identity)
        float fr = exp2f(-10.0f * (float)lane / 15.0f);
        float th = (float)t * fr;
        float s, c;
        sincosf(th, &s, &c);
        float y0 =  v0 * c + v1 * s;
        float y1 = -v0 * s + v1 * c;
        v0 = y0; v1 = y1;
    }
    p[lane]      = v0;
    p[lane + 32] = v1;
}

// ---------------------------------------------------------------------------
// Causal flash attention, fp32 SIMT. BM=BN=64, D=64, 256 threads (16x16),
// each thread owns a 4x4 tile of S/P and a 4x4 tile of O.
// Dynamic smem: Qs|Ks|Vs, each 64 x 65 floats. P is staged through Ks.
// ---------------------------------------------------------------------------
#define LDS 65
__global__ void flash_kernel()
{
    extern __shared__ float sm[];
    float* Qs = sm;
    float* Ks = Qs + 64 * LDS;
    float* Vs = Ks + 64 * LDS;

    const int qb = blockIdx.x;      // query block
    const int h  = blockIdx.y;
    const int tid = threadIdx.x;
    const int tx = tid & 15;
    const int ty = tid >> 4;

    const float* q = g_qkv + (size_t)(0 * HEADS + h) * (T_SEQ * HEAD_D);
    const float* k = g_qkv + (size_t)(1 * HEADS + h) * (T_SEQ * HEAD_D);
    const float* v = g_qkv + (size_t)(2 * HEADS + h) * (T_SEQ * HEAD_D);

    // load Q tile (pre-scaled)
    for (int i = tid; i < 64 * 16; i += 256) {
        int r  = i >> 4;
        int c4 = (i & 15) * 4;
        float4 qv = *(const float4*)&q[(size_t)(qb * 64 + r) * HEAD_D + c4];
        Qs[r * LDS + c4 + 0] = qv.x * ATTN_SCALE;
        Qs[r * LDS + c4 + 1] = qv.y * ATTN_SCALE;
        Qs[r * LDS + c4 + 2] = qv.z * ATTN_SCALE;
        Qs[r * LDS + c4 + 3] = qv.w * ATTN_SCALE;
    }

    float m_i[4], l_i[4], acc[4][4];
    #pragma unroll
    for (int i = 0; i < 4; i++) {
        m_i[i] = -FLT_MAX; l_i[i] = 0.0f;
        #pragma unroll
        for (int j = 0; j < 4; j++) acc[i][j] = 0.0f;
    }

    for (int kb = 0; kb <= qb; kb++) {
        __syncthreads();   // protect Ks/Vs from previous iteration's readers
        for (int i = tid; i < 64 * 16; i += 256) {
            int r  = i >> 4;
            int c4 = (i & 15) * 4;
            float4 kv = *(const float4*)&k[(size_t)(kb * 64 + r) * HEAD_D + c4];
            Ks[r * LDS + c4 + 0] = kv.x; Ks[r * LDS + c4 + 1] = kv.y;
            Ks[r * LDS + c4 + 2] = kv.z; Ks[r * LDS + c4 + 3] = kv.w;
            float4 vv = *(const float4*)&v[(size_t)(kb * 64 + r) * HEAD_D + c4];
            Vs[r * LDS + c4 + 0] = vv.x; Vs[r * LDS + c4 + 1] = vv.y;
            Vs[r * LDS + c4 + 2] = vv.z; Vs[r * LDS + c4 + 3] = vv.w;
        }
        __syncthreads();

        // S = Qs @ Ks^T  (4x4 per thread)
        float s[4][4] = {};
        #pragma unroll 8
        for (int d = 0; d < 64; d++) {
            float a[4], b[4];
            #pragma unroll
            for (int i = 0; i < 4; i++) a[i] = Qs[(4 * ty + i) * LDS + d];
            #pragma unroll
            for (int j = 0; j < 4; j++) b[j] = Ks[(4 * tx + j) * LDS + d];
            #pragma unroll
            for (int i = 0; i < 4; i++)
                #pragma unroll
                for (int j = 0; j < 4; j++)
                    s[i][j] += a[i] * b[j];
        }

        // causal mask on the diagonal block
        if (kb == qb) {
            #pragma unroll
            for (int i = 0; i < 4; i++)
                #pragma unroll
                for (int j = 0; j < 4; j++)
                    if (4 * tx + j > 4 * ty + i) s[i][j] = -FLT_MAX;
        }

        // row max (reduce over j, then over the 16 tx lanes)
        float mt[4];
        #pragma unroll
        for (int i = 0; i < 4; i++) {
            mt[i] = fmaxf(fmaxf(s[i][0], s[i][1]), fmaxf(s[i][2], s[i][3]));
            #pragma unroll
            for (int off = 1; off < 16; off <<= 1)
                mt[i] = fmaxf(mt[i], __shfl_xor_sync(0xffffffffu, mt[i], off));
        }

        float alpha[4], rs[4];
        #pragma unroll
        for (int i = 0; i < 4; i++) {
            float mnew = fmaxf(m_i[i], mt[i]);
            alpha[i] = __expf(m_i[i] - mnew);
            m_i[i] = mnew;
            float sum = 0.0f;
            #pragma unroll
            for (int j = 0; j < 4; j++) {
                s[i][j] = __expf(s[i][j] - mnew);   // now P
                sum += s[i][j];
            }
            rs[i] = sum;
        }
        #pragma unroll
        for (int i = 0; i < 4; i++) {
            #pragma unroll
            for (int off = 1; off < 16; off <<= 1)
                rs[i] += __shfl_xor_sync(0xffffffffu, rs[i], off);
            l_i[i] = l_i[i] * alpha[i] + rs[i];
            #pragma unroll
            for (int j = 0; j < 4; j++) acc[i][j] *= alpha[i];
        }

        // stage P through Ks (all S reads of Ks are done)
        __syncthreads();
        #pragma unroll
        for (int i = 0; i < 4; i++)
            #pragma unroll
            for (int j = 0; j < 4; j++)
                Ks[(4 * ty + i) * LDS + 4 * tx + j] = s[i][j];
        __syncthreads();

        // O += P @ V
        #pragma unroll 8
        for (int j2 = 0; j2 < 64; j2++) {
            float a[4], b[4];
            #pragma unroll
            for (int i = 0; i < 4; i++) a[i] = Ks[(4 * ty + i) * LDS + j2];
            #pragma unroll
            for (int j = 0; j < 4; j++) b[j] = Vs[j2 * LDS + 4 * tx + j];
            #pragma unroll
            for (int i = 0; i < 4; i++)
                #pragma unroll
                for (int j = 0; j < 4; j++)
                    acc[i][j] += a[i] * b[j];
        }
    }

    // write y[t][h*64 + c] = O / l
    #pragma unroll
    for (int i = 0; i < 4; i++) {
        int t = qb * 64 + 4 * ty + i;
        float inv_l = 1.0f / l_i[i];
        #pragma unroll
        for (int j = 0; j < 4; j++)
            g_y[(size_t)t * DIM + h * HEAD_D + 4 * tx + j] = acc[i][j] * inv_l;
    }
}

// ---------------------------------------------------------------------------

extern "C" void kernel_launch(void* const* d_in, const int* in_sizes, int n_in,
                              void* d_out, int out_size)
{
    const float* x        = (const float*)d_in[0];   // [1, 4096, 768]
    const float* qkv_w    = (const float*)d_in[1];   // [3, 768, 768]
    const float* c_proj_w = (const float*)d_in[2];   // [768, 768]
    float* out            = (float*)d_out;           // [4096, 768]

    // 1) QKV projection with head-major scatter
    gemm_qkv_kernel<<<dim3(T_SEQ / 64, N_QKV / 64), 256>>>(x, qkv_w);

    // 2) RMSNorm + rope on q, k
    rms_rope_kernel<<<T_SEQ, 2 * HEADS * 32>>>();

    // 3) causal flash attention
    const int smem = 3 * 64 * LDS * sizeof(float);   // 49920 B
    cudaFuncSetAttribute(flash_kernel,
                         cudaFuncAttributeMaxDynamicSharedMemorySize, smem);
    flash_kernel<<<dim3(T_SEQ / 64, HEADS), 256, smem>>>();

    // 4) output projection
    gemm_proj_kernel<<<dim3(T_SEQ / 64, DIM / 64), 256>>>(c_proj_w, out);
}

// round 2
// speedup vs baseline: 3.1314x; 3.1314x over previous
#include <cuda_runtime.h>
#include <cuda_bf16.h>
#include <float.h>
#include <stdint.h>

typedef __nv_bfloat16 bf16;

#define T_SEQ   4096
#define DIM     768
#define HEADS   12
#define HEAD_D  64
#define N_QKV   (3 * DIM)
#define RMS_EPS 1.1920928955078125e-07f
#define ATTN_SCALE 0.12f

// ---------------- scratch (device globals; no allocation) -------------------
__device__ float g_qkv[3 * HEADS * T_SEQ * HEAD_D];          // f32 qkv, head-major
__device__ bf16  g_sp_hi[3 * HEADS * T_SEQ * HEAD_D];        // q/k/v hi (q pre-scaled)
__device__ bf16  g_sp_lo[3 * HEADS * T_SEQ * HEAD_D];
__device__ bf16  g_xh[T_SEQ * DIM],  g_xl[T_SEQ * DIM];
__device__ bf16  g_wqh[N_QKV * DIM], g_wql[N_QKV * DIM];
__device__ bf16  g_wph[DIM * DIM],   g_wpl[DIM * DIM];
__device__ bf16  g_yh[T_SEQ * DIM],  g_yl[T_SEQ * DIM];

// ---------------- small helpers --------------------------------------------
__device__ __forceinline__ uint32_t smem_u32(const void* p) {
    return (uint32_t)__cvta_generic_to_shared(p);
}
__device__ __forceinline__ void ldsm_x4(uint32_t& r0, uint32_t& r1,
                                        uint32_t& r2, uint32_t& r3, uint32_t a) {
    asm volatile("ldmatrix.sync.aligned.m8n8.x4.shared.b16 {%0,%1,%2,%3},[%4];\n"
                 : "=r"(r0), "=r"(r1), "=r"(r2), "=r"(r3) : "r"(a));
}
__device__ __forceinline__ void ldsm_x4_t(uint32_t& r0, uint32_t& r1,
                                          uint32_t& r2, uint32_t& r3, uint32_t a) {
    asm volatile("ldmatrix.sync.aligned.m8n8.x4.trans.shared.b16 {%0,%1,%2,%3},[%4];\n"
                 : "=r"(r0), "=r"(r1), "=r"(r2), "=r"(r3) : "r"(a));
}
__device__ __forceinline__ void mma16816(float* d, const uint32_t* a, const uint32_t* b) {
    asm volatile(
        "mma.sync.aligned.m16n8k16.row.col.f32.bf16.bf16.f32 "
        "{%0,%1,%2,%3},{%4,%5,%6,%7},{%8,%9},{%0,%1,%2,%3};\n"
        : "+f"(d[0]), "+f"(d[1]), "+f"(d[2]), "+f"(d[3])
        : "r"(a[0]), "r"(a[1]), "r"(a[2]), "r"(a[3]), "r"(b[0]), "r"(b[1]));
}
__device__ __forceinline__ uint32_t pack_bf2(float x, float y) {
    __nv_bfloat162 t = __floats2bfloat162_rn(x, y);
    return *(uint32_t*)&t;
}
__device__ __forceinline__ void split_f(float v, bf16& h, bf16& l) {
    h = __float2bfloat16(v);
    l = __float2bfloat16(v - __bfloat162float(h));
}

// ---------------- f32 -> (hi, lo) bf16 split --------------------------------
__global__ void split_kernel(const float* __restrict__ in,
                             bf16* __restrict__ hi, bf16* __restrict__ lo, int n) {
    int i = blockIdx.x * blockDim.x + threadIdx.x;
    if (i < n) {
        bf16 h, l; split_f(in[i], h, l);
        hi[i] = h; lo[i] = l;
    }
}

// ---------------- GEMM: C = A @ B^T, 3-term bf16 split ----------------------
// Block tile 128x64, 256 threads, warps 4(m) x 2(n), warp tile 32x32.
#define LDA 40
template<int MODE>   // 0: scatter into g_qkv ; 1: plain write to C
__global__ __launch_bounds__(256) void gemm_mma_kernel(
    const bf16* __restrict__ Ah, const bf16* __restrict__ Al,
    const bf16* __restrict__ Bh, const bf16* __restrict__ Bl,
    float* __restrict__ C)
{
    constexpr int K = 768;
    __shared__ bf16 sA[2][128][LDA];
    __shared__ bf16 sB[2][64][LDA];
    const int tid = threadIdx.x;
    const int wid = tid >> 5, lane = tid & 31;
    const int wm = wid & 3, wn = wid >> 2;
    const int m0 = blockIdx.x * 128, n0 = blockIdx.y * 64;
    const int g = lane >> 2, q = lane & 3;

    float acc[2][4][4];
    #pragma unroll
    for (int a = 0; a < 2; a++)
        #pragma unroll
        for (int b = 0; b < 4; b++)
            #pragma unroll
            for (int c = 0; c < 4; c++) acc[a][b][c] = 0.f;

    for (int k0 = 0; k0 < K; k0 += 32) {
        __syncthreads();
        #pragma unroll
        for (int i = 0; i < 2; i++) {
            int c = tid + i * 256;               // 0..511
            int r = c >> 2, col = (c & 3) * 8;
            size_t go = (size_t)(m0 + r) * K + k0 + col;
            *(uint4*)&sA[0][r][col] = *(const uint4*)(Ah + go);
            *(uint4*)&sA[1][r][col] = *(const uint4*)(Al + go);
        }
        {
            int r = tid >> 2, col = (tid & 3) * 8;
            size_t go = (size_t)(n0 + r) * K + k0 + col;
            *(uint4*)&sB[0][r][col] = *(const uint4*)(Bh + go);
            *(uint4*)&sB[1][r][col] = *(const uint4*)(Bl + go);
        }
        __syncthreads();

        uint32_t aF[2][2][2][4];   // [hi/lo][mt][kt][4]
        uint32_t bF[2][4][2][2];   // [hi/lo][nt][kt][2]
        #pragma unroll
        for (int v = 0; v < 2; v++) {
            #pragma unroll
            for (int mt = 0; mt < 2; mt++)
                #pragma unroll
                for (int kt = 0; kt < 2; kt++) {
                    uint32_t ad = smem_u32(&sA[v][wm * 32 + mt * 16 + (lane & 15)]
                                              [kt * 16 + (lane >> 4) * 8]);
                    ldsm_x4(aF[v][mt][kt][0], aF[v][mt][kt][1],
                            aF[v][mt][kt][2], aF[v][mt][kt][3], ad);
                }
            #pragma unroll
            for (int np = 0; np < 2; np++)
                #pragma unroll
                for (int kt = 0; kt < 2; kt++) {
                    uint32_t ad = smem_u32(&sB[v][wn * 32 + np * 16 + (lane & 15)]
                                              [kt * 16 + (lane >> 4) * 8]);
                    uint32_t r0, r1, r2, r3;
                    ldsm_x4(r0, r1, r2, r3, ad);
                    bF[v][np * 2 + 0][kt][0] = r0; bF[v][np * 2 + 1][kt][0] = r1;
                    bF[v][np * 2 + 0][kt][1] = r2; bF[v][np * 2 + 1][kt][1] = r3;
                }
        }
        #pragma unroll
        for (int mt = 0; mt < 2; mt++)
            #pragma unroll
            for (int nt = 0; nt < 4; nt++)
                #pragma unroll
                for (int kt = 0; kt < 2; kt++) {
                    mma16816(acc[mt][nt], aF[0][mt][kt], bF[0][nt][kt]);
                    mma16816(acc[mt][nt], aF[0][mt][kt], bF[1][nt][kt]);
                    mma16816(acc[mt][nt], aF[1][mt][kt], bF[0][nt][kt]);
                }
    }

    #pragma unroll
    for (int mt = 0; mt < 2; mt++)
        #pragma unroll
        for (int nt = 0; nt < 4; nt++) {
            int r0 = m0 + wm * 32 + mt * 16 + g;
            int cc = n0 + wn * 32 + nt * 8 + q * 2;
            float* a = acc[mt][nt];
            if (MODE == 0) {
                size_t base = (size_t)(cc >> 6) * (T_SEQ * HEAD_D) + (cc & 63);
                *(float2*)&g_qkv[base + (size_t)r0 * HEAD_D]       = make_float2(a[0], a[1]);
                *(float2*)&g_qkv[base + (size_t)(r0 + 8) * HEAD_D] = make_float2(a[2], a[3]);
            } else {
                *(float2*)&C[(size_t)r0 * DIM + cc]       = make_float2(a[0], a[1]);
                *(float2*)&C[(size_t)(r0 + 8) * DIM + cc] = make_float2(a[2], a[3]);
            }
        }
}

// ---------------- RMSNorm + rotary + split (q,k) ; split (v) ----------------
// grid (T_SEQ, 3), block 384 (12 warps = 12 heads). blockIdx.y = comp.
__global__ void rms_rope_split_kernel() {
    const int t = blockIdx.x;
    const int comp = blockIdx.y;
    const int h = threadIdx.x >> 5;
    const int lane = threadIdx.x & 31;
    const size_t off = ((size_t)(comp * HEADS + h)) * (T_SEQ * HEAD_D) + (size_t)t * HEAD_D;
    const float* p = g_qkv + off;
    float v0 = p[lane], v1 = p[lane + 32];

    if (comp < 2) {
        float ss = v0 * v0 + v1 * v1;
        #pragma unroll
        for (int o = 16; o >= 1; o >>= 1) ss += __shfl_xor_sync(0xffffffffu, ss, o);
        float r = rsqrtf(ss * (1.0f / HEAD_D) + RMS_EPS);
        v0 *= r; v1 *= r;
        if (lane < 16) {
            float fr = exp2f(-10.0f * (float)lane / 15.0f);
            float th = (float)t * fr, s, c;
            sincosf(th, &s, &c);
            float y0 =  v0 * c + v1 * s;
            float y1 = -v0 * s + v1 * c;
            v0 = y0; v1 = y1;
        }
        if (comp == 0) { v0 *= ATTN_SCALE; v1 *= ATTN_SCALE; }
    }
    bf16 h0, l0, h1, l1;
    split_f(v0, h0, l0);
    split_f(v1, h1, l1);
    g_sp_hi[off + lane] = h0;      g_sp_lo[off + lane] = l0;
    g_sp_hi[off + lane + 32] = h1; g_sp_lo[off + lane + 32] = l1;
}

// ---------------- Flash attention on mma ------------------------------------
// Block: one 64-row query tile x one head. 4 warps; warp w owns rows 16w..16w+15.
#define FLD 72
__global__ __launch_bounds__(128) void flash_mma_kernel() {
    __shared__ bf16 sK[2][64][FLD];
    __shared__ bf16 sV[2][64][FLD];
    const int qb = (gridDim.x - 1) - blockIdx.x;    // heavy blocks first
    const int h = blockIdx.y;
    const int tid = threadIdx.x, wid = tid >> 5, lane = tid & 31;
    const int g = lane >> 2, q = lane & 3;

    const size_t HS = (size_t)T_SEQ * HEAD_D;
    const bf16* Qh = g_sp_hi + (0 * HEADS + h) * HS;
    const bf16* Ql = g_sp_lo + (0 * HEADS + h) * HS;
    const bf16* Kh = g_sp_hi + (1 * HEADS + h) * HS;
    const bf16* Kl = g_sp_lo + (1 * HEADS + h) * HS;
    const bf16* Vh = g_sp_hi + (2 * HEADS + h) * HS;
    const bf16* Vl = g_sp_lo + (2 * HEADS + h) * HS;

    // Q fragments straight from global (row-major pairs are contiguous)
    uint32_t qF[2][4][4];
    {
        int r0 = qb * 64 + wid * 16 + g;
        #pragma unroll
        for (int v = 0; v < 2; v++) {
            const bf16* Qp = v ? Ql : Qh;
            #pragma unroll
            for (int kt = 0; kt < 4; kt++) {
                int c = kt * 16 + q * 2;
                qF[v][kt][0] = *(const uint32_t*)(Qp + (size_t)r0 * HEAD_D + c);
                qF[v][kt][1] = *(const uint32_t*)(Qp + (size_t)(r0 + 8) * HEAD_D + c);
                qF[v][kt][2] = *(const uint32_t*)(Qp + (size_t)r0 * HEAD_D + c + 8);
                qF[v][kt][3] = *(const uint32_t*)(Qp + (size_t)(r0 + 8) * HEAD_D + c + 8);
            }
        }
    }

    float o[8][4];
    #pragma unroll
    for (int i = 0; i < 8; i++)
        #pragma unroll
        for (int j = 0; j < 4; j++) o[i][j] = 0.f;
    float m0_ = -1e30f, m1_ = -1e30f, l0_ = 0.f, l1_ = 0.f;

    for (int kb = 0; kb <= qb; kb++) {
        __syncthreads();
        #pragma unroll
        for (int i = 0; i < 4; i++) {
            int c = tid + i * 128;               // 0..511
            int r = c >> 3, col = (c & 7) * 8;
            size_t go = (size_t)(kb * 64 + r) * HEAD_D + col;
            *(uint4*)&sK[0][r][col] = *(const uint4*)(Kh + go);
            *(uint4*)&sK[1][r][col] = *(const uint4*)(Kl + go);
            *(uint4*)&sV[0][r][col] = *(const uint4*)(Vh + go);
            *(uint4*)&sV[1][r][col] = *(const uint4*)(Vl + go);
        }
        __syncthreads();

        // ---- S = Q K^T (3-term) ----
        float s[8][4];
        #pragma unroll
        for (int i = 0; i < 8; i++)
            #pragma unroll
            for (int j = 0; j < 4; j++) s[i][j] = 0.f;

        #pragma unroll
        for (int kt = 0; kt < 4; kt++) {
            uint32_t bh[8][2], bl[8][2];
            #pragma unroll
            for (int np = 0; np < 4; np++) {
                uint32_t ad = smem_u32(&sK[0][np * 16 + (lane & 15)]
                                          [kt * 16 + (lane >> 4) * 8]);
                uint32_t r0, r1, r2, r3;
                ldsm_x4(r0, r1, r2, r3, ad);
                bh[np * 2][0] = r0; bh[np * 2 + 1][0] = r1;
                bh[np * 2][1] = r2; bh[np * 2 + 1][1] = r3;
                ad = smem_u32(&sK[1][np * 16 + (lane & 15)]
                                  [kt * 16 + (lane >> 4) * 8]);
                ldsm_x4(r0, r1, r2, r3, ad);
                bl[np * 2][0] = r0; bl[np * 2 + 1][0] = r1;
                bl[np * 2][1] = r2; bl[np * 2 + 1][1] = r3;
            }
            #pragma unroll
            for (int nt = 0; nt < 8; nt++) {
                mma16816(s[nt], qF[0][kt], bh[nt]);
                mma16816(s[nt], qF[0][kt], bl[nt]);
                mma16816(s[nt], qF[1][kt], bh[nt]);
            }
        }

        // ---- mask + online softmax ----
        if (kb == qb) {
            int r0 = wid * 16 + g, r1 = r0 + 8;
            #pragma unroll
            for (int nt = 0; nt < 8; nt++) {
                int c0 = nt * 8 + q * 2, c1 = c0 + 1;
                if (c0 > r0) s[nt][0] = -1e30f;
                if (c1 > r0) s[nt][1] = -1e30f;
                if (c0 > r1) s[nt][2] = -1e30f;
                if (c1 > r1) s[nt][3] = -1e30f;
            }
        }
        float mt0 = -1e30f, mt1 = -1e30f;
        #pragma unroll
        for (int nt = 0; nt < 8; nt++) {
            mt0 = fmaxf(mt0, fmaxf(s[nt][0], s[nt][1]));
            mt1 = fmaxf(mt1, fmaxf(s[nt][2], s[nt][3]));
        }
        mt0 = fmaxf(mt0, __shfl_xor_sync(0xffffffffu, mt0, 1));
        mt0 = fmaxf(mt0, __shfl_xor_sync(0xffffffffu, mt0, 2));
        mt1 = fmaxf(mt1, __shfl_xor_sync(0xffffffffu, mt1, 1));
        mt1 = fmaxf(mt1, __shfl_xor_sync(0xffffffffu, mt1, 2));

        float mn0 = fmaxf(m0_, mt0), mn1 = fmaxf(m1_, mt1);
        float al0 = __expf(m0_ - mn0), al1 = __expf(m1_ - mn1);
        m0_ = mn0; m1_ = mn1;

        float rs0 = 0.f, rs1 = 0.f;
        #pragma unroll
        for (int nt = 0; nt < 8; nt++) {
            s[nt][0] = __expf(s[nt][0] - mn0);
            s[nt][1] = __expf(s[nt][1] - mn0);
            s[nt][2] = __expf(s[nt][2] - mn1);
            s[nt][3] = __expf(s[nt][3] - mn1);
            rs0 += s[nt][0] + s[nt][1];
            rs1 += s[nt][2] + s[nt][3];
        }
        rs0 += __shfl_xor_sync(0xffffffffu, rs0, 1);
        rs0 += __shfl_xor_sync(0xffffffffu, rs0, 2);
        rs1 += __shfl_xor_sync(0xffffffffu, rs1, 1);
        rs1 += __shfl_xor_sync(0xffffffffu, rs1, 2);
        l0_ = l0_ * al0 + rs0;
        l1_ = l1_ * al1 + rs1;
        #pragma unroll
        for (int nt = 0; nt < 8; nt++) {
            o[nt][0] *= al0; o[nt][1] *= al0;
            o[nt][2] *= al1; o[nt][3] *= al1;
        }

        // ---- P -> a-fragments (hi/lo) ----
        uint32_t pF[2][4][4];
        #pragma unroll
        for (int kt = 0; kt < 4; kt++) {
            #pragma unroll
            for (int half = 0; half < 2; half++) {       // nt = 2kt+half
                float p0 = s[2 * kt + half][0], p1 = s[2 * kt + half][1];
                float p2 = s[2 * kt + half][2], p3 = s[2 * kt + half][3];
                float h0 = __bfloat162float(__float2bfloat16(p0));
                float h1 = __bfloat162float(__float2bfloat16(p1));
                float h2 = __bfloat162float(__float2bfloat16(p2));
                float h3 = __bfloat162float(__float2bfloat16(p3));
                pF[0][kt][0 + 2 * half] = pack_bf2(h0, h1);
                pF[0][kt][1 + 2 * half] = pack_bf2(h2, h3);
                pF[1][kt][0 + 2 * half] = pack_bf2(p0 - h0, p1 - h1);
                pF[1][kt][1 + 2 * half] = pack_bf2(p2 - h2, p3 - h3);
            }
        }

        // ---- O += P V (3-term) ----
        #pragma unroll
        for (int kt = 0; kt < 4; kt++) {
            uint32_t bvh[8][2], bvl[8][2];
            #pragma unroll
            for (int np = 0; np < 4; np++) {
                uint32_t ad = smem_u32(&sV[0][kt * 16 + (lane & 15)]
                                          [np * 16 + (lane >> 4) * 8]);
                uint32_t r0, r1, r2, r3;
                ldsm_x4_t(r0, r1, r2, r3, ad);
                bvh[np * 2][0] = r0; bvh[np * 2][1] = r1;       // note order (trans)
                bvh[np * 2 + 1][0] = r2; bvh[np * 2 + 1][1] = r3;
                ad = smem_u32(&sV[1][kt * 16 + (lane & 15)]
                                  [np * 16 + (lane >> 4) * 8]);
                ldsm_x4_t(r0, r1, r2, r3, ad);
                bvl[np * 2][0] = r0; bvl[np * 2][1] = r1;
                bvl[np * 2 + 1][0] = r2; bvl[np * 2 + 1][1] = r3;
            }
            #pragma unroll
            for (int nt = 0; nt < 8; nt++) {
                mma16816(o[nt], pF[0][kt], bvh[nt]);
                mma16816(o[nt], pF[0][kt], bvl[nt]);
                mma16816(o[nt], pF[1][kt], bvh[nt]);
            }
        }
    }

    // ---- epilogue: y = O / l, split hi/lo ----
    float i0 = 1.f / l0_, i1 = 1.f / l1_;
    int t0 = qb * 64 + wid * 16 + g;
    #pragma unroll
    for (int nt = 0; nt < 8; nt++) {
        int d = h * HEAD_D + nt * 8 + q * 2;
        float y0 = o[nt][0] * i0, y1 = o[nt][1] * i0;
        float y2 = o[nt][2] * i1, y3 = o[nt][3] * i1;
        float h0 = __bfloat162float(__float2bfloat16(y0));
        float h1 = __bfloat162float(__float2bfloat16(y1));
        float h2 = __bfloat162float(__float2bfloat16(y2));
        float h3 = __bfloat162float(__float2bfloat16(y3));
        *(uint32_t*)&g_yh[(size_t)t0 * DIM + d]       = pack_bf2(h0, h1);
        *(uint32_t*)&g_yh[(size_t)(t0 + 8) * DIM + d] = pack_bf2(h2, h3);
        *(uint32_t*)&g_yl[(size_t)t0 * DIM + d]       = pack_bf2(y0 - h0, y1 - h1);
        *(uint32_t*)&g_yl[(size_t)(t0 + 8) * DIM + d] = pack_bf2(y2 - h2, y3 - h3);
    }
}

// ---------------------------------------------------------------------------
extern "C" void kernel_launch(void* const* d_in, const int* in_sizes, int n_in,
                              void* d_out, int out_size)
{
    const float* x        = (const float*)d_in[0];
    const float* qkv_w    = (const float*)d_in[1];
    const float* c_proj_w = (const float*)d_in[2];
    float* out            = (float*)d_out;

    bf16 *xh, *xl, *wqh, *wql, *wph, *wpl;
    cudaGetSymbolAddress((void**)&xh,  g_xh);  cudaGetSymbolAddress((void**)&xl,  g_xl);
    cudaGetSymbolAddress((void**)&wqh, g_wqh); cudaGetSymbolAddress((void**)&wql, g_wql);
    cudaGetSymbolAddress((void**)&wph, g_wph); cudaGetSymbolAddress((void**)&wpl, g_wpl);
    bf16 *yh, *yl;
    cudaGetSymbolAddress((void**)&yh, g_yh);   cudaGetSymbolAddress((void**)&yl, g_yl);

    // 0) split inputs into bf16 hi/lo
    {
        int n1 = T_SEQ * DIM, n2 = N_QKV * DIM, n3 = DIM * DIM;
        split_kernel<<<(n1 + 255) / 256, 256>>>(x, xh, xl, n1);
        split_kernel<<<(n2 + 255) / 256, 256>>>(qkv_w, wqh, wql, n2);
        split_kernel<<<(n3 + 255) / 256, 256>>>(c_proj_w, wph, wpl, n3);
    }

    // 1) QKV projection (tensor cores) -> g_qkv f32 head-major
    gemm_mma_kernel<0><<<dim3(T_SEQ / 128, N_QKV / 64), 256>>>(xh, xl, wqh, wql, nullptr);

    // 2) rms + rope + bf16 split (q scaled); v split
    rms_rope_split_kernel<<<dim3(T_SEQ, 3), HEADS * 32>>>();

    // 3) flash attention (tensor cores) -> g_y hi/lo
    flash_mma_kernel<<<dim3(T_SEQ / 64, HEADS), 128>>>();

    // 4) output projection (tensor cores) -> out
    gemm_mma_kernel<1><<<dim3(T_SEQ / 128, DIM / 64), 256>>>(yh, yl, wph, wpl, out);
}